// round 17
// baseline (speedup 1.0000x reference)
#include <cuda_runtime.h>
#include <math.h>

#define N_NODES   20000
#define N_EDGES   320000
#define MUL0      64
#define NODE_DIM  240          // 64 + 3*32 + 5*16
#define NUM_BASIS 16
#define NCH       112          // 64 + 32 + 16 fused channels
#define NSTAT     144          // 9 * 16 sufficient statistics per node
#define INV_SQRT_MAXAT 0.0916698497028211f   // 1/sqrt(119)

// Fused projection matrices
__device__ float g_M[NUM_BASIS * NCH];
// Per-node sufficient statistics: G[n][j][b] = sum_e sh_e[j] * rbf_e[b]
__device__ float g_stats[(size_t)N_NODES * NSTAT];
// counting-sort state
__device__ int g_deg[N_NODES];
__device__ int g_offs[N_NODES + 1];
__device__ int g_cursor[N_NODES];
__device__ int g_sorted[N_EDGES];

// ---------------------------------------------------------------------------
// K1: fused M (first 1792 warps, proven short+wide shape) + zero stats
//     (grid-stride; also L2 pre-warm for atomics) + zero degree histogram.
// ---------------------------------------------------------------------------
__global__ void __launch_bounds__(256)
setup_kernel(const float* __restrict__ W_rbf,
             const float* __restrict__ w_expand,
             const float* __restrict__ b_expand,
             const float* __restrict__ Wp0,
             const float* __restrict__ Wp1,
             const float* __restrict__ Wp2)
{
    int tid = blockIdx.x * blockDim.x + threadIdx.x;

    // ---- fused M: one warp per output element ----
    int w    = tid >> 5;
    int lane = threadIdx.x & 31;
    if (w < NUM_BASIS * NCH) {
        int b  = w / NCH;
        int ch = w % NCH;

        int   roff;
        const float* Wp;
        int   K, d;
        if (ch < 64)       { roff = 0;   Wp = Wp0; K = 64; d = ch; }
        else if (ch < 96)  { roff = 64;  Wp = Wp1; K = 32; d = ch - 64; }
        else               { roff = 128; Wp = Wp2; K = 16; d = ch - 96; }

        float acc = 0.f;
        #pragma unroll
        for (int h = 0; h < 2; ++h) {
            int c = lane + 32 * h;
            acc = fmaf(W_rbf[b * 192 + roff + c] * (w_expand[c] + b_expand[c]),
                       Wp[c * K + d], acc);
        }
        #pragma unroll
        for (int off = 16; off > 0; off >>= 1)
            acc += __shfl_xor_sync(0xffffffffu, acc, off);

        if (lane == 0) g_M[b * NCH + ch] = acc * 0.125f;   // * 1/sqrt(64)
    }

    // ---- zero degree histogram (int4) ----
    if (tid < N_NODES / 4)
        ((int4*)g_deg)[tid] = make_int4(0, 0, 0, 0);

    // ---- zero stats as float4 (also L2 pre-warm) ----
    const int n4 = N_NODES * NSTAT / 4;
    float4 z = make_float4(0.f, 0.f, 0.f, 0.f);
    for (int i = tid; i < n4; i += gridDim.x * blockDim.x)
        ((float4*)g_stats)[i] = z;
}

// ---------------------------------------------------------------------------
// K2: dst histogram, 4 edges/thread (MLP)
// ---------------------------------------------------------------------------
__global__ void __launch_bounds__(256)
hist_kernel(const int* __restrict__ edge_index)
{
    int base = (blockIdx.x * blockDim.x + threadIdx.x) * 4;
    #pragma unroll
    for (int q = 0; q < 4; ++q) {
        int e = base + q;
        if (e < N_EDGES) atomicAdd(&g_deg[edge_index[N_EDGES + e]], 1);
    }
}

// ---------------------------------------------------------------------------
// K3: single-block exclusive scan over 20000 bins (verified in R2)
// ---------------------------------------------------------------------------
__global__ void scan_kernel()
{
    __shared__ int sh[1024];
    const int CHUNK = 20;              // 1024*20 = 20480 >= 20000
    int t = threadIdx.x;
    int base = t * CHUNK;
    int local[CHUNK];
    int sum = 0;
    #pragma unroll
    for (int i = 0; i < CHUNK; ++i) {
        int idx = base + i;
        int v = (idx < N_NODES) ? g_deg[idx] : 0;
        local[i] = sum;
        sum += v;
    }
    sh[t] = sum;
    __syncthreads();
    for (int off = 1; off < 1024; off <<= 1) {
        int v = (t >= off) ? sh[t - off] : 0;
        __syncthreads();
        sh[t] += v;
        __syncthreads();
    }
    int pre = (t > 0) ? sh[t - 1] : 0;
    #pragma unroll
    for (int i = 0; i < CHUNK; ++i) {
        int idx = base + i;
        if (idx < N_NODES) {
            int o = pre + local[i];
            g_offs[idx]   = o;
            g_cursor[idx] = o;
        }
    }
    if (t == 1023) g_offs[N_NODES] = sh[1023];
}

// ---------------------------------------------------------------------------
// K4: scatter edge ids into dst-sorted order, 4 edges/thread (MLP)
// ---------------------------------------------------------------------------
__global__ void __launch_bounds__(256)
scatter_kernel(const int* __restrict__ edge_index)
{
    int base = (blockIdx.x * blockDim.x + threadIdx.x) * 4;
    #pragma unroll
    for (int q = 0; q < 4; ++q) {
        int e = base + q;
        if (e < N_EDGES) {
            int dst = edge_index[N_EDGES + e];
            int p = atomicAdd(&g_cursor[dst], 1);
            g_sorted[p] = e;
        }
    }
}

// ---------------------------------------------------------------------------
// Vectorized L2 reduction
// ---------------------------------------------------------------------------
__device__ __forceinline__ void red_add_v4(float* addr, float a, float b, float c, float d)
{
    asm volatile("red.global.add.v4.f32 [%0], {%1,%2,%3,%4};"
                 :: "l"(addr), "f"(a), "f"(b), "f"(c), "f"(d) : "memory");
}

// ---------------------------------------------------------------------------
// K5: edge kernel over DST-SORTED edges. Per-thread rbf/rsh compute + direct
//     (scattered) output stores; flush accumulates RUNS of equal dst in
//     registers and emits one coalesced red.v4 set per run (~2-3 per warp
//     instead of ~20).
// ---------------------------------------------------------------------------
#define EK_THREADS 128
#define ROWSTRIDE  28          // floats; 112B, 16B-aligned

__device__ __forceinline__ void flush_node(int dst, int lane,
                                           const float4& acc, const float4& accT)
{
    float* S = g_stats + (size_t)dst * NSTAT;
    red_add_v4(S + 4 * lane, acc.x, acc.y, acc.z, acc.w);
    if (lane < 4)
        red_add_v4(S + 128 + 4 * lane, accT.x, accT.y, accT.z, accT.w);
}

__global__ void __launch_bounds__(EK_THREADS)
edge_kernel(const float* __restrict__ pos,
            const int*   __restrict__ edge_index,
            float*       __restrict__ rbf_out,
            float*       __restrict__ rsh_out)
{
    __shared__ float sbuf[4][32][ROWSTRIDE];   // [warp][slot][0:16 rbf |16:25 sh]
    __shared__ int   sdst[4][32];

    int tid  = threadIdx.x;
    int warp = tid >> 5;
    int lane = tid & 31;

    int e = g_sorted[blockIdx.x * EK_THREADS + tid];   // dst-sorted edge id

    bool active = false;
    float* mybuf = sbuf[warp][lane];

    {
        int src = edge_index[e];
        int dst = edge_index[N_EDGES + e];
        sdst[warp][lane] = dst;

        const float* Ps = pos + 3 * src;
        const float* Pd = pos + 3 * dst;
        // reference permutes pos columns to [1,2,0] before differencing
        float vx = Pd[1] - Ps[1];
        float vy = Pd[2] - Ps[2];
        float vz = Pd[0] - Ps[0];

        float d2   = vx * vx + vy * vy + vz * vz;
        float dist = sqrtf(d2);
        float dcl  = fmaxf(dist, 1e-8f);
        float uinv = 1.0f / dcl;
        float x = vx * uinv, y = vy * uinv, z = vz * uinv;

        const float s3  = 1.7320508075688772f;
        const float s5  = 2.23606797749979f;
        const float s15 = 3.872983346207417f;

        float sh[9];
        sh[0] = 1.f;
        sh[1] = s3 * x;
        sh[2] = s3 * y;
        sh[3] = s3 * z;
        sh[4] = s15 * x * z;
        sh[5] = s15 * x * y;
        sh[6] = s5 * (y * y - 0.5f * (x * x + z * z));
        sh[7] = s15 * y * z;
        sh[8] = 0.5f * s15 * (z * z - x * x);

        float rbf[16];
        active = (dcl < 5.0f);
        if (active) {
            float X  = dcl * 0.2f;
            float X2 = X * X;
            float X5 = X2 * X2 * X;
            float fc = 1.0f + X5 * (-21.0f + X * (35.0f - 15.0f * X));
            float theta = 3.14159265358979323846f * X;
            // precise sinf/cosf: fast path destroys tiny theta (self loops)
            float s1 = sinf(theta), c1 = cosf(theta);
            float two  = 2.0f * c1;
            float pref = 0.6324555320336759f * uinv * fc;   // sqrt(2/5)/d * fc
            float sp = 0.f, s = s1;
            #pragma unroll
            for (int n = 0; n < 16; ++n) {
                rbf[n] = pref * s;
                float sn = two * s - sp;
                sp = s; s = sn;
            }
        } else {
            #pragma unroll
            for (int n = 0; n < 16; ++n) rbf[n] = 0.f;
        }

        // direct output stores at ORIGINAL edge position (scattered)
        {
            float4* ro = (float4*)(rbf_out + (size_t)e * 16);
            #pragma unroll
            for (int q = 0; q < 4; ++q)
                ro[q] = make_float4(rbf[4*q], rbf[4*q+1], rbf[4*q+2], rbf[4*q+3]);
            float* rs = rsh_out + (size_t)e * 9;
            #pragma unroll
            for (int j = 0; j < 9; ++j) rs[j] = sh[j];
        }

        #pragma unroll
        for (int i = 0; i < 16; ++i) mybuf[i] = rbf[i];
        #pragma unroll
        for (int j = 0; j < 9; ++j)  mybuf[16 + j] = sh[j];
    }

    unsigned act = __ballot_sync(0xffffffffu, active);
    __syncwarp();

    // run-aggregated flush over the warp's 32 dst-sorted edges
    {
        int cur = sdst[warp][0];
        float4 acc  = make_float4(0.f, 0.f, 0.f, 0.f);
        float4 accT = make_float4(0.f, 0.f, 0.f, 0.f);
        bool dirty = false;

        #pragma unroll 4
        for (int k = 0; k < 32; ++k) {
            int d = sdst[warp][k];
            if (d != cur) {
                if (dirty) {
                    flush_node(cur, lane, acc, accT);
                    acc  = make_float4(0.f, 0.f, 0.f, 0.f);
                    accT = make_float4(0.f, 0.f, 0.f, 0.f);
                    dirty = false;
                }
                cur = d;
            }
            if ((act >> k) & 1u) {
                const float* eb = sbuf[warp][k];
                float  sj = eb[16 + (lane >> 2)];
                float4 r  = *(const float4*)(eb + ((lane & 3) << 2));
                acc.x = fmaf(sj, r.x, acc.x);
                acc.y = fmaf(sj, r.y, acc.y);
                acc.z = fmaf(sj, r.z, acc.z);
                acc.w = fmaf(sj, r.w, acc.w);
                if (lane < 4) {
                    float  s8 = eb[24];
                    float4 r2 = *(const float4*)(eb + (lane << 2));
                    accT.x = fmaf(s8, r2.x, accT.x);
                    accT.y = fmaf(s8, r2.y, accT.y);
                    accT.z = fmaf(s8, r2.z, accT.z);
                    accT.w = fmaf(s8, r2.w, accT.w);
                }
                dirty = true;
            }
        }
        if (dirty) flush_node(cur, lane, acc, accT);
    }
}

// ---------------------------------------------------------------------------
// K6: node projection, M in registers, G via LDS.128 (proven shape).
// ---------------------------------------------------------------------------
#define NB              4      // nodes per sync round
#define NODES_PER_BLOCK 32

__device__ __forceinline__ void task_desc(int t, int& goff, int& moff,
                                          int& chbase, int& stride)
{
    if (t < 16) {             // path0
        goff = 0; moff = 4 * t; chbase = 4 * t; stride = 1;
    } else if (t < 40) {      // path1
        int p = t - 16, m = p >> 3, g = p & 7;
        goff = (1 + m) * 16; moff = 64 + 4 * g;
        chbase = 64 + 12 * g + m; stride = 3;
    } else {                  // path2
        int p = t - 40, m = p >> 2, g = p & 3;
        goff = (4 + m) * 16; moff = 96 + 4 * g;
        chbase = 160 + 20 * g + m; stride = 5;
    }
}

__global__ void __launch_bounds__(128)
node_kernel(const int*   __restrict__ at_no,
            const float* __restrict__ W_atom,
            const float* __restrict__ b_atom,
            float*       __restrict__ node_emb)
{
    __shared__ __align__(16) float sG[NB * NSTAT];   // 4 nodes x 144

    int t = threadIdx.x;
    bool tvalid = (t < 120);

    int task = t >> 1, half = t & 1;
    int goff = 0, moff = 0, chbase = 0, stride = 1;
    if (tvalid) task_desc(task, goff, moff, chbase, stride);
    int col0 = moff + 2 * half;
    int ch0  = chbase + (2 * half) * stride;
    int ch1  = chbase + (2 * half + 1) * stride;

    float m0[16], m1[16];
    float2 ba = make_float2(0.f, 0.f);
    if (tvalid) {
        #pragma unroll
        for (int b = 0; b < 16; ++b) {
            m0[b] = g_M[b * NCH + col0];
            m1[b] = g_M[b * NCH + col0 + 1];
        }
        if (t < 32) ba = *(const float2*)(b_atom + ch0);
    }

    int nbase0 = blockIdx.x * NODES_PER_BLOCK;

    for (int it = 0; it < NODES_PER_BLOCK / NB; ++it) {
        int nbase = nbase0 + it * NB;

        __syncthreads();
        {
            const float4* Sp = (const float4*)(g_stats + (size_t)nbase * NSTAT);
            float4* Dp = (float4*)sG;
            Dp[t] = Sp[t];
            if (t < 16) Dp[128 + t] = Sp[128 + t];
        }
        __syncthreads();

        if (tvalid) {
            #pragma unroll
            for (int k = 0; k < NB; ++k) {
                int n = nbase + k;
                const float4* G4 = (const float4*)(sG + k * NSTAT + goff);
                float a0 = 0.f, a1 = 0.f;
                #pragma unroll
                for (int q = 0; q < 4; ++q) {
                    float4 g = G4[q];
                    a0 = fmaf(g.x, m0[4*q+0], a0); a1 = fmaf(g.x, m1[4*q+0], a1);
                    a0 = fmaf(g.y, m0[4*q+1], a0); a1 = fmaf(g.y, m1[4*q+1], a1);
                    a0 = fmaf(g.z, m0[4*q+2], a0); a1 = fmaf(g.z, m1[4*q+2], a1);
                    a0 = fmaf(g.w, m0[4*q+3], a0); a1 = fmaf(g.w, m1[4*q+3], a1);
                }
                float* nrow = node_emb + (size_t)n * NODE_DIM;
                if (t < 32) {
                    int an = at_no[n];
                    float2 wa = *(const float2*)(W_atom + an * MUL0 + ch0);
                    a0 += fmaf(wa.x, INV_SQRT_MAXAT, ba.x);
                    a1 += fmaf(wa.y, INV_SQRT_MAXAT, ba.y);
                    *(float2*)(nrow + ch0) = make_float2(a0, a1);
                } else {
                    nrow[ch0] = a0;
                    nrow[ch1] = a1;
                }
            }
        }
    }
}

// ---------------------------------------------------------------------------
// Launch
// ---------------------------------------------------------------------------
extern "C" void kernel_launch(void* const* d_in, const int* in_sizes, int n_in,
                              void* d_out, int out_size)
{
    const int*   at_no      = (const int*)  d_in[0];
    const float* pos        = (const float*)d_in[1];
    const int*   edge_index = (const int*)  d_in[2];
    const float* W_atom     = (const float*)d_in[3];
    const float* b_atom     = (const float*)d_in[4];
    const float* w_expand   = (const float*)d_in[5];
    const float* b_expand   = (const float*)d_in[6];
    const float* W_rbf      = (const float*)d_in[7];
    const float* Wp0        = (const float*)d_in[8];
    const float* Wp1        = (const float*)d_in[9];
    const float* Wp2        = (const float*)d_in[10];

    float* out      = (float*)d_out;
    float* node_emb = out;                                   // 20000*240
    float* rbf_out  = out + (size_t)N_NODES * NODE_DIM;      // 320000*16
    float* rsh_out  = rbf_out + (size_t)N_EDGES * NUM_BASIS; // 320000*9

    setup_kernel<<<224, 256>>>(W_rbf, w_expand, b_expand, Wp0, Wp1, Wp2);
    hist_kernel<<<(N_EDGES / 4 + 255) / 256, 256>>>(edge_index);
    scan_kernel<<<1, 1024>>>();
    scatter_kernel<<<(N_EDGES / 4 + 255) / 256, 256>>>(edge_index);
    edge_kernel<<<N_EDGES / EK_THREADS, EK_THREADS>>>(
        pos, edge_index, rbf_out, rsh_out);
    node_kernel<<<N_NODES / NODES_PER_BLOCK, 128>>>(at_no, W_atom, b_atom, node_emb);
}